// round 8
// baseline (speedup 1.0000x reference)
#include <cuda_runtime.h>
#include <cuda_fp16.h>
#include <cstdint>

#define B_  2
#define C_  256
#define H8  56
#define W8  96
#define HW  5376            // H8*W8
#define NQ  (B_*HW)         // 10752 query rows (batch-major)

// ---------------- scratch (static __device__, no allocations) ----------------
__device__ __align__(128) __half g_f1[B_*HW*C_];   // fmap1 [b][n][c] fp16
__device__ __align__(128) __half g_f2[B_*HW*C_];   // fmap2 [b][m][c] fp16
__device__ __align__(128) __half g_c0[57802752];   // 2*5376*5376 level-0 corr
__device__ __align__(128) __half g_c1[NQ*28*48];
__device__ __align__(128) __half g_c2[NQ*14*24];
__device__ __align__(128) __half g_c3[NQ*7*12];

// ---------------- helpers ----------------
__device__ __forceinline__ uint32_t smem_u32(const void* p) {
    return (uint32_t)__cvta_generic_to_shared(p);
}
__device__ __forceinline__ void ldm4(uint32_t& r0, uint32_t& r1, uint32_t& r2, uint32_t& r3,
                                     uint32_t addr) {
    asm volatile("ldmatrix.sync.aligned.m8n8.x4.shared.b16 {%0,%1,%2,%3}, [%4];"
                 : "=r"(r0), "=r"(r1), "=r"(r2), "=r"(r3) : "r"(addr));
}
__device__ __forceinline__ void mma16816(float* c, const uint32_t* a, const uint32_t* b) {
    asm volatile(
        "mma.sync.aligned.m16n8k16.row.col.f32.f16.f16.f32 "
        "{%0,%1,%2,%3},{%4,%5,%6,%7},{%8,%9},{%0,%1,%2,%3};"
        : "+f"(c[0]), "+f"(c[1]), "+f"(c[2]), "+f"(c[3])
        : "r"(a[0]), "r"(a[1]), "r"(a[2]), "r"(a[3]), "r"(b[0]), "r"(b[1]));
}
__device__ __forceinline__ void cpasync16(uint32_t dst, const void* src) {
    asm volatile("cp.async.cg.shared.global [%0], [%1], 16;" :: "r"(dst), "l"(src));
}
__device__ __forceinline__ void cp_commit() {
    asm volatile("cp.async.commit_group;" ::: "memory");
}
template<int N> __device__ __forceinline__ void cp_wait() {
    asm volatile("cp.async.wait_group %0;" :: "n"(N) : "memory");
}

// empty kernel: shifts the profiled launch index onto k_gemm (diagnostics)
__global__ void k_nop() {}

// ---------------- 1) transpose + fp16 convert: [B,C,H,W] -> [B,HW,C] ----------------
__global__ void k_convert(const float* __restrict__ f1, const float* __restrict__ f2) {
    __shared__ float tile[32][33];
    int t = blockIdx.z >> 1;
    int b = blockIdx.z & 1;
    const float* src = t ? f2 : f1;
    __half* dst = t ? g_f2 : g_f1;
    int n0 = blockIdx.x * 32, c0 = blockIdx.y * 32;
    int tx = threadIdx.x, ty = threadIdx.y;
    tile[ty][tx] = src[(size_t)(b * C_ + c0 + ty) * HW + n0 + tx];
    __syncthreads();
    dst[(size_t)(b * HW + n0 + ty) * C_ + c0 + tx] = __float2half_rn(tile[tx][ty]);
}

// ---------------- 2) corr GEMM (HMMA, K64 chunks, 2-stage cp.async, staged epilogue) --
#define SSTRIDE 72          // 64 halfs + 8 pad
#define EPSTRIDE 136        // epilogue staging stride (halfs), conflict-free

__global__ __launch_bounds__(256, 2) void k_gemm() {
    __shared__ __align__(16) __half As[2][128 * SSTRIDE];
    __shared__ __align__(16) __half Bs[2][128 * SSTRIDE];
    const int b  = blockIdx.z;
    const int bi = blockIdx.y;
    const int bj = blockIdx.x;
    const int tid  = threadIdx.x;
    const int lane = tid & 31;
    const int wid  = tid >> 5;
    const int wm = (wid & 1) * 64;
    const int wn = (wid >> 1) * 32;

    const __half* Ag = g_f1 + ((size_t)b * HW + (size_t)bi * 128) * C_;
    const __half* Bg = g_f2 + ((size_t)b * HW + (size_t)bj * 128) * C_;

    float acc[4][4][4];
#pragma unroll
    for (int i = 0; i < 4; i++)
#pragma unroll
        for (int j = 0; j < 4; j++)
#pragma unroll
            for (int k = 0; k < 4; k++) acc[i][j][k] = 0.f;

    // per stage: 128 rows x 64 halfs (128B) per operand; 4 int4 each per thread
#define LOAD_STAGE64(kt, s)                                                        \
    {                                                                              \
        const int k0 = (kt) * 64;                                                  \
        _Pragma("unroll")                                                          \
        for (int it = 0; it < 4; it++) {                                           \
            int idx = tid + it * 256;          /* 0..1023 */                       \
            int row = idx >> 3;                                                    \
            int c   = (idx & 7) << 3;          /* half offset, 16B units */        \
            cpasync16(smem_u32(&As[s][row * SSTRIDE + c]),                         \
                      Ag + row * C_ + k0 + c);                                     \
            cpasync16(smem_u32(&Bs[s][row * SSTRIDE + c]),                         \
                      Bg + row * C_ + k0 + c);                                     \
        }                                                                          \
        cp_commit();                                                               \
    }

    LOAD_STAGE64(0, 0);

#pragma unroll
    for (int kt = 0; kt < 4; kt++) {
        __syncthreads();                     // all warps done with chunk kt-1
        if (kt < 3) { LOAD_STAGE64(kt + 1, (kt + 1) & 1); }
        else        { cp_commit(); }
        cp_wait<1>();                        // chunk kt resident
        __syncthreads();                     // loads of kt visible to all warps
        const __half* as = As[kt & 1];
        const __half* bs = Bs[kt & 1];
#pragma unroll
        for (int kk = 0; kk < 64; kk += 16) {
            uint32_t a[4][4], bf[4][2];
#pragma unroll
            for (int mi = 0; mi < 4; mi++) {
                int row = wm + mi * 16 + (lane & 15);
                int col = kk + ((lane >> 4) << 3);
                ldm4(a[mi][0], a[mi][1], a[mi][2], a[mi][3],
                     smem_u32(as + row * SSTRIDE + col));
            }
#pragma unroll
            for (int nb = 0; nb < 2; nb++) {
                int row = wn + nb * 16 + (lane & 7) + ((lane >> 4) << 3);
                int col = kk + (((lane >> 3) & 1) << 3);
                uint32_t r0, r1, r2, r3;
                ldm4(r0, r1, r2, r3, smem_u32(bs + row * SSTRIDE + col));
                bf[nb * 2][0] = r0; bf[nb * 2][1] = r1;
                bf[nb * 2 + 1][0] = r2; bf[nb * 2 + 1][1] = r3;
            }
#pragma unroll
            for (int mi = 0; mi < 4; mi++)
#pragma unroll
                for (int ni = 0; ni < 4; ni++)
                    mma16816(acc[mi][ni], a[mi], bf[ni]);
        }
    }

    // ---- epilogue: acc -> smem stage (conflict-free) -> coalesced st.128 ----
    __syncthreads();                       // all warps done reading As/Bs
    __half* stage = &As[0][0];             // 128 x EPSTRIDE halfs = 34816 B (< 36864)
    const float s = 0.0625f;               // 1/sqrt(256)
#pragma unroll
    for (int mi = 0; mi < 4; mi++) {
#pragma unroll
        for (int ni = 0; ni < 4; ni++) {
            int r0 = wm + mi * 16 + (lane >> 2);
            int c0 = wn + ni * 8 + (lane & 3) * 2;
            *(__half2*)(stage + r0 * EPSTRIDE + c0) =
                __floats2half2_rn(acc[mi][ni][0] * s, acc[mi][ni][1] * s);
            *(__half2*)(stage + (r0 + 8) * EPSTRIDE + c0) =
                __floats2half2_rn(acc[mi][ni][2] * s, acc[mi][ni][3] * s);
        }
    }
    __syncthreads();
    const size_t rowb = (size_t)b * HW + (size_t)bi * 128;
#pragma unroll
    for (int it = 0; it < 8; it++) {
        int r  = wid * 16 + it * 2 + (lane >> 4);   // 0..127
        int ci = lane & 15;                         // int4 index within 256B row
        int4 v = *(const int4*)(stage + r * EPSTRIDE + ci * 8);
        *(int4*)(g_c0 + (rowb + r) * HW + (size_t)bj * 128 + ci * 8) = v;
    }
}

// ---------------- 3) fused pyramid pool: c0 row -> l1,l2,l3 ----------------
__global__ void k_pool_fused() {
    __shared__ __align__(16) __half s0[56 * 96];
    __shared__ __half s1[28 * 48];
    __shared__ __half s2[14 * 24];
    int n = blockIdx.x;
    int tid = threadIdx.x;
    const int4* src = (const int4*)(g_c0 + (size_t)n * 5376);
    int4* s0v = (int4*)s0;
#pragma unroll
    for (int i = tid; i < 672; i += 256) s0v[i] = src[i];
    __syncthreads();
    for (int i = tid; i < 1344; i += 256) {
        int x = i % 48, y = i / 48;
        float v = 0.25f * (__half2float(s0[(2 * y) * 96 + 2 * x]) +
                           __half2float(s0[(2 * y) * 96 + 2 * x + 1]) +
                           __half2float(s0[(2 * y + 1) * 96 + 2 * x]) +
                           __half2float(s0[(2 * y + 1) * 96 + 2 * x + 1]));
        __half h = __float2half_rn(v);
        s1[i] = h;
        g_c1[(size_t)n * 1344 + i] = h;
    }
    __syncthreads();
    for (int i = tid; i < 336; i += 256) {
        int x = i % 24, y = i / 24;
        float v = 0.25f * (__half2float(s1[(2 * y) * 48 + 2 * x]) +
                           __half2float(s1[(2 * y) * 48 + 2 * x + 1]) +
                           __half2float(s1[(2 * y + 1) * 48 + 2 * x]) +
                           __half2float(s1[(2 * y + 1) * 48 + 2 * x + 1]));
        __half h = __float2half_rn(v);
        s2[i] = h;
        g_c2[(size_t)n * 336 + i] = h;
    }
    __syncthreads();
    if (tid < 84) {
        int x = tid % 12, y = tid / 12;
        float v = 0.25f * (__half2float(s2[(2 * y) * 24 + 2 * x]) +
                           __half2float(s2[(2 * y) * 24 + 2 * x + 1]) +
                           __half2float(s2[(2 * y + 1) * 24 + 2 * x]) +
                           __half2float(s2[(2 * y + 1) * 24 + 2 * x + 1]));
        g_c3[(size_t)n * 84 + tid] = __float2half_rn(v);
    }
}

// ---------------- 4) pyramid sampling, coalesced stores -> [B,324,H8,W8] ----------------
__global__ __launch_bounds__(128) void k_sample(const float* __restrict__ coords,
                                                float* __restrict__ out) {
    __shared__ __half swin[4][100][32];
    int blk = blockIdx.x;            // 2*56*3 = 336
    int wseg = blk % 3;
    int h = (blk / 3) % H8;
    int b = blk / (3 * H8);
    int tx = threadIdx.x;            // pixel within 32-segment
    int L  = threadIdx.y;            // level
    int w = wseg * 32 + tx;
    int nq = h * W8 + w;

    float cx = coords[(size_t)(b * 2 + 0) * HW + nq];
    float cy = coords[(size_t)(b * 2 + 1) * HW + nq];

    const __half* cl; int Hl, Wl;
    if (L == 0)      { cl = g_c0; Hl = 56; Wl = 96; }
    else if (L == 1) { cl = g_c1; Hl = 28; Wl = 48; }
    else if (L == 2) { cl = g_c2; Hl = 14; Wl = 24; }
    else             { cl = g_c3; Hl = 7;  Wl = 12; }

    float inv = 1.0f / (float)(1 << L);
    float fx = cx * inv, fy = cy * inv;
    float fxf = floorf(fx), fyf = floorf(fy);
    float wx = fx - fxf, wy = fy - fyf;
    int bx = (int)fxf - 4, by = (int)fyf - 4;

    const __half* base = cl + (size_t)(b * HW + nq) * (Hl * Wl);
#pragma unroll
    for (int ly = 0; ly < 10; ly++) {
        int gy = by + ly;
        bool yok = (gy >= 0) & (gy < Hl);
        const __half* rowp = base + gy * Wl;
#pragma unroll
        for (int lx = 0; lx < 10; lx++) {
            int gx = bx + lx;
            __half v = __float2half_rn(0.f);
            if (yok && gx >= 0 && gx < Wl) v = rowp[gx];
            swin[L][ly * 10 + lx][tx] = v;
        }
    }
    __syncthreads();

    float* outbase = out + ((size_t)(b * 324 + L * 81) * H8 + h) * W8 + w;
#pragma unroll 3
    for (int o = 0; o < 81; o++) {
        int xo = o / 9;              // x varies along axis 0 (torch meshgrid quirk)
        int yo = o % 9;
        float v00 = __half2float(swin[L][yo * 10 + xo][tx]);
        float v10 = __half2float(swin[L][yo * 10 + xo + 1][tx]);
        float v01 = __half2float(swin[L][(yo + 1) * 10 + xo][tx]);
        float v11 = __half2float(swin[L][(yo + 1) * 10 + xo + 1][tx]);
        float v = (1.f - wy) * ((1.f - wx) * v00 + wx * v10)
                +        wy  * ((1.f - wx) * v01 + wx * v11);
        outbase[(size_t)o * HW] = v;
    }
}

// ---------------- 5) convex upsample -> [B,2,448,768] ----------------
__global__ void k_up(const float* __restrict__ flow, const float* __restrict__ mask,
                     float* __restrict__ out) {
    int id = blockIdx.x;
    int rs = id & 63;
    int bh = id >> 6;
    int h = bh % H8;
    int b = bh / H8;
    int w = threadIdx.x;
    int r = rs >> 3, s = rs & 7;

    float f0[9], f1v[9];
#pragma unroll
    for (int k = 0; k < 9; k++) {
        int i = k / 3 - 1, j = k % 3 - 1;
        int hh = h + i, ww = w + j;
        bool ok = (hh >= 0 && hh < H8 && ww >= 0 && ww < W8);
        f0[k]  = ok ? flow[((size_t)(b * 2 + 0) * H8 + hh) * W8 + ww] : 0.f;
        f1v[k] = ok ? flow[((size_t)(b * 2 + 1) * H8 + hh) * W8 + ww] : 0.f;
    }
    float e[9], sum = 0.f;
#pragma unroll
    for (int k = 0; k < 9; k++) {
        e[k] = __expf(mask[((size_t)(b * 576 + k * 64 + rs) * H8 + h) * W8 + w]);
        sum += e[k];
    }
    float a0 = 0.f, a1 = 0.f;
#pragma unroll
    for (int k = 0; k < 9; k++) { a0 += e[k] * f0[k]; a1 += e[k] * f1v[k]; }
    float inv = 8.0f / sum;
    int y = h * 8 + r, x = w * 8 + s;
    out[((size_t)(b * 2 + 0) * 448 + y) * 768 + x] = a0 * inv;
    out[((size_t)(b * 2 + 1) * 448 + y) * 768 + x] = a1 * inv;
}

// ---------------- launcher ----------------
extern "C" void kernel_launch(void* const* d_in, const int* in_sizes, int n_in,
                              void* d_out, int out_size) {
    const float* fmap1  = (const float*)d_in[0];
    const float* fmap2  = (const float*)d_in[1];
    const float* coords = (const float*)d_in[2];
    const float* flow   = (const float*)d_in[3];
    const float* mask   = (const float*)d_in[4];
    float* out = (float*)d_out;
    float* out_up = out + (size_t)B_ * 324 * HW;

    dim3 cb(32, 32);
    k_convert<<<dim3(HW / 32, C_ / 32, 4), cb>>>(fmap1, fmap2);     // idx 0
    k_nop<<<1, 32>>>();                                             // idx 1
    k_nop<<<1, 32>>>();                                             // idx 2
    k_gemm<<<dim3(42, 42, 2), 256>>>();                             // idx 3 (profiled)
    k_pool_fused<<<NQ, 256>>>();                                    // idx 4
    k_sample<<<336, dim3(32, 4)>>>(coords, out);                    // idx 5
    k_up<<<NQ * 64 / W8, W8>>>(flow, mask, out_up);                 // idx 6
}

// round 9
// speedup vs baseline: 1.0462x; 1.0462x over previous
#include <cuda_runtime.h>
#include <cuda_fp16.h>
#include <cstdint>

#define B_  2
#define C_  256
#define H8  56
#define W8  96
#define HW  5376            // H8*W8
#define NQ  (B_*HW)         // 10752 query rows (batch-major)

// ---------------- scratch (static __device__, no allocations) ----------------
__device__ __align__(128) __half g_f1[B_*HW*C_];   // fmap1 [b][n][c] fp16
__device__ __align__(128) __half g_f2[B_*HW*C_];   // fmap2 [b][m][c] fp16
__device__ __align__(128) __half g_c0[57802752];   // 2*5376*5376 level-0 corr
__device__ __align__(128) __half g_c1[NQ*28*48];
__device__ __align__(128) __half g_c2[NQ*14*24];
__device__ __align__(128) __half g_c3[NQ*7*12];

// ---------------- helpers ----------------
__device__ __forceinline__ uint32_t smem_u32(const void* p) {
    return (uint32_t)__cvta_generic_to_shared(p);
}
__device__ __forceinline__ void ldm4(uint32_t& r0, uint32_t& r1, uint32_t& r2, uint32_t& r3,
                                     uint32_t addr) {
    asm volatile("ldmatrix.sync.aligned.m8n8.x4.shared.b16 {%0,%1,%2,%3}, [%4];"
                 : "=r"(r0), "=r"(r1), "=r"(r2), "=r"(r3) : "r"(addr));
}
__device__ __forceinline__ void mma16816(float* c, const uint32_t* a, const uint32_t* b) {
    asm volatile(
        "mma.sync.aligned.m16n8k16.row.col.f32.f16.f16.f32 "
        "{%0,%1,%2,%3},{%4,%5,%6,%7},{%8,%9},{%0,%1,%2,%3};"
        : "+f"(c[0]), "+f"(c[1]), "+f"(c[2]), "+f"(c[3])
        : "r"(a[0]), "r"(a[1]), "r"(a[2]), "r"(a[3]), "r"(b[0]), "r"(b[1]));
}
__device__ __forceinline__ void cpasync16(uint32_t dst, const void* src) {
    asm volatile("cp.async.cg.shared.global [%0], [%1], 16;" :: "r"(dst), "l"(src));
}
__device__ __forceinline__ void cp_commit() {
    asm volatile("cp.async.commit_group;" ::: "memory");
}
template<int N> __device__ __forceinline__ void cp_wait() {
    asm volatile("cp.async.wait_group %0;" :: "n"(N) : "memory");
}

// empty kernel: shifts the profiled launch index onto k_gemm (diagnostics)
__global__ void k_nop() {}

// ---------------- 1) transpose + fp16 convert: [B,C,H,W] -> [B,HW,C] ----------------
__global__ void k_convert(const float* __restrict__ f1, const float* __restrict__ f2) {
    __shared__ float tile[32][33];
    int t = blockIdx.z >> 1;
    int b = blockIdx.z & 1;
    const float* src = t ? f2 : f1;
    __half* dst = t ? g_f2 : g_f1;
    int n0 = blockIdx.x * 32, c0 = blockIdx.y * 32;
    int tx = threadIdx.x, ty = threadIdx.y;
    tile[ty][tx] = src[(size_t)(b * C_ + c0 + ty) * HW + n0 + tx];
    __syncthreads();
    dst[(size_t)(b * HW + n0 + ty) * C_ + c0 + tx] = __float2half_rn(tile[tx][ty]);
}

// ---------------- 2) corr GEMM: 128 thr, 4 warps x (64x64), K64 2-stage cp.async ------
#define SSTRIDE 72          // 64 halfs + 8 pad
#define EPSTRIDE 136        // epilogue staging stride (halfs), conflict-free

__global__ __launch_bounds__(128, 2) void k_gemm() {
    __shared__ __align__(16) __half As[2][128 * SSTRIDE];
    __shared__ __align__(16) __half Bs[2][128 * SSTRIDE];
    const int b  = blockIdx.z;
    const int bi = blockIdx.y;
    const int bj = blockIdx.x;
    const int tid  = threadIdx.x;
    const int lane = tid & 31;
    const int wid  = tid >> 5;
    const int wm = (wid & 1) * 64;    // 2 warps along M
    const int wn = (wid >> 1) * 64;   // 2 warps along N

    const __half* Ag = g_f1 + ((size_t)b * HW + (size_t)bi * 128) * C_;
    const __half* Bg = g_f2 + ((size_t)b * HW + (size_t)bj * 128) * C_;

    float acc[4][8][4];
#pragma unroll
    for (int i = 0; i < 4; i++)
#pragma unroll
        for (int j = 0; j < 8; j++)
#pragma unroll
            for (int k = 0; k < 4; k++) acc[i][j][k] = 0.f;

    // per stage: 128 rows x 64 halfs (128B) per operand; 8 int4 each per thread
#define LOAD_STAGE64(kt, s)                                                        \
    {                                                                              \
        const int k0 = (kt) * 64;                                                  \
        _Pragma("unroll")                                                          \
        for (int it = 0; it < 8; it++) {                                           \
            int idx = tid + it * 128;          /* 0..1023 */                       \
            int row = idx >> 3;                                                    \
            int c   = (idx & 7) << 3;                                              \
            cpasync16(smem_u32(&As[s][row * SSTRIDE + c]),                         \
                      Ag + row * C_ + k0 + c);                                     \
            cpasync16(smem_u32(&Bs[s][row * SSTRIDE + c]),                         \
                      Bg + row * C_ + k0 + c);                                     \
        }                                                                          \
        cp_commit();                                                               \
    }

    LOAD_STAGE64(0, 0);

#pragma unroll
    for (int kt = 0; kt < 4; kt++) {
        __syncthreads();                     // all warps done with chunk kt-1
        if (kt < 3) { LOAD_STAGE64(kt + 1, (kt + 1) & 1); }
        else        { cp_commit(); }
        cp_wait<1>();                        // chunk kt resident
        __syncthreads();                     // loads of kt visible to all warps
        const __half* as = As[kt & 1];
        const __half* bs = Bs[kt & 1];
#pragma unroll
        for (int kk = 0; kk < 64; kk += 16) {
            uint32_t a[4][4], bf[8][2];
#pragma unroll
            for (int mi = 0; mi < 4; mi++) {
                int row = wm + mi * 16 + (lane & 15);
                int col = kk + ((lane >> 4) << 3);
                ldm4(a[mi][0], a[mi][1], a[mi][2], a[mi][3],
                     smem_u32(as + row * SSTRIDE + col));
            }
#pragma unroll
            for (int nb = 0; nb < 4; nb++) {
                int row = wn + nb * 16 + (lane & 7) + ((lane >> 4) << 3);
                int col = kk + (((lane >> 3) & 1) << 3);
                uint32_t r0, r1, r2, r3;
                ldm4(r0, r1, r2, r3, smem_u32(bs + row * SSTRIDE + col));
                bf[nb * 2][0] = r0; bf[nb * 2][1] = r1;
                bf[nb * 2 + 1][0] = r2; bf[nb * 2 + 1][1] = r3;
            }
#pragma unroll
            for (int mi = 0; mi < 4; mi++)
#pragma unroll
                for (int ni = 0; ni < 8; ni++)
                    mma16816(acc[mi][ni], a[mi], bf[ni]);
        }
    }

    // ---- epilogue: acc -> smem stage (conflict-free) -> coalesced st.128 ----
    __syncthreads();                       // all warps done reading As/Bs
    __half* stage = &As[0][0];             // 128 x EPSTRIDE halfs = 34816 B
    const float s = 0.0625f;               // 1/sqrt(256)
#pragma unroll
    for (int mi = 0; mi < 4; mi++) {
#pragma unroll
        for (int ni = 0; ni < 8; ni++) {
            int r0 = wm + mi * 16 + (lane >> 2);
            int c0 = wn + ni * 8 + (lane & 3) * 2;
            *(__half2*)(stage + r0 * EPSTRIDE + c0) =
                __floats2half2_rn(acc[mi][ni][0] * s, acc[mi][ni][1] * s);
            *(__half2*)(stage + (r0 + 8) * EPSTRIDE + c0) =
                __floats2half2_rn(acc[mi][ni][2] * s, acc[mi][ni][3] * s);
        }
    }
    __syncthreads();
    const size_t rowb = (size_t)b * HW + (size_t)bi * 128;
#pragma unroll
    for (int it = 0; it < 16; it++) {
        int idx = tid + it * 128;
        int r  = idx >> 4;                          // 0..127
        int ci = idx & 15;                          // int4 index within 256B row
        int4 v = *(const int4*)(stage + r * EPSTRIDE + ci * 8);
        *(int4*)(g_c0 + (rowb + r) * HW + (size_t)bj * 128 + ci * 8) = v;
    }
}

// ---------------- 3) fused pyramid pool: c0 row -> l1,l2,l3 ----------------
__global__ void k_pool_fused() {
    __shared__ __align__(16) __half s0[56 * 96];
    __shared__ __half s1[28 * 48];
    __shared__ __half s2[14 * 24];
    int n = blockIdx.x;
    int tid = threadIdx.x;
    const int4* src = (const int4*)(g_c0 + (size_t)n * 5376);
    int4* s0v = (int4*)s0;
#pragma unroll
    for (int i = tid; i < 672; i += 256) s0v[i] = src[i];
    __syncthreads();
    for (int i = tid; i < 1344; i += 256) {
        int x = i % 48, y = i / 48;
        float v = 0.25f * (__half2float(s0[(2 * y) * 96 + 2 * x]) +
                           __half2float(s0[(2 * y) * 96 + 2 * x + 1]) +
                           __half2float(s0[(2 * y + 1) * 96 + 2 * x]) +
                           __half2float(s0[(2 * y + 1) * 96 + 2 * x + 1]));
        __half h = __float2half_rn(v);
        s1[i] = h;
        g_c1[(size_t)n * 1344 + i] = h;
    }
    __syncthreads();
    for (int i = tid; i < 336; i += 256) {
        int x = i % 24, y = i / 24;
        float v = 0.25f * (__half2float(s1[(2 * y) * 48 + 2 * x]) +
                           __half2float(s1[(2 * y) * 48 + 2 * x + 1]) +
                           __half2float(s1[(2 * y + 1) * 48 + 2 * x]) +
                           __half2float(s1[(2 * y + 1) * 48 + 2 * x + 1]));
        __half h = __float2half_rn(v);
        s2[i] = h;
        g_c2[(size_t)n * 336 + i] = h;
    }
    __syncthreads();
    if (tid < 84) {
        int x = tid % 12, y = tid / 12;
        float v = 0.25f * (__half2float(s2[(2 * y) * 24 + 2 * x]) +
                           __half2float(s2[(2 * y) * 24 + 2 * x + 1]) +
                           __half2float(s2[(2 * y + 1) * 24 + 2 * x]) +
                           __half2float(s2[(2 * y + 1) * 24 + 2 * x + 1]));
        g_c3[(size_t)n * 84 + tid] = __float2half_rn(v);
    }
}

// ---------------- 4) pyramid sampling, coalesced stores -> [B,324,H8,W8] ----------------
__global__ __launch_bounds__(128) void k_sample(const float* __restrict__ coords,
                                                float* __restrict__ out) {
    __shared__ __half swin[4][100][32];
    int blk = blockIdx.x;            // 2*56*3 = 336
    int wseg = blk % 3;
    int h = (blk / 3) % H8;
    int b = blk / (3 * H8);
    int tx = threadIdx.x;            // pixel within 32-segment
    int L  = threadIdx.y;            // level
    int w = wseg * 32 + tx;
    int nq = h * W8 + w;

    float cx = coords[(size_t)(b * 2 + 0) * HW + nq];
    float cy = coords[(size_t)(b * 2 + 1) * HW + nq];

    const __half* cl; int Hl, Wl;
    if (L == 0)      { cl = g_c0; Hl = 56; Wl = 96; }
    else if (L == 1) { cl = g_c1; Hl = 28; Wl = 48; }
    else if (L == 2) { cl = g_c2; Hl = 14; Wl = 24; }
    else             { cl = g_c3; Hl = 7;  Wl = 12; }

    float inv = 1.0f / (float)(1 << L);
    float fx = cx * inv, fy = cy * inv;
    float fxf = floorf(fx), fyf = floorf(fy);
    float wx = fx - fxf, wy = fy - fyf;
    int bx = (int)fxf - 4, by = (int)fyf - 4;

    const __half* base = cl + (size_t)(b * HW + nq) * (Hl * Wl);
#pragma unroll
    for (int ly = 0; ly < 10; ly++) {
        int gy = by + ly;
        bool yok = (gy >= 0) & (gy < Hl);
        const __half* rowp = base + gy * Wl;
#pragma unroll
        for (int lx = 0; lx < 10; lx++) {
            int gx = bx + lx;
            __half v = __float2half_rn(0.f);
            if (yok && gx >= 0 && gx < Wl) v = rowp[gx];
            swin[L][ly * 10 + lx][tx] = v;
        }
    }
    __syncthreads();

    float* outbase = out + ((size_t)(b * 324 + L * 81) * H8 + h) * W8 + w;
#pragma unroll 3
    for (int o = 0; o < 81; o++) {
        int xo = o / 9;              // x varies along axis 0 (torch meshgrid quirk)
        int yo = o % 9;
        float v00 = __half2float(swin[L][yo * 10 + xo][tx]);
        float v10 = __half2float(swin[L][yo * 10 + xo + 1][tx]);
        float v01 = __half2float(swin[L][(yo + 1) * 10 + xo][tx]);
        float v11 = __half2float(swin[L][(yo + 1) * 10 + xo + 1][tx]);
        float v = (1.f - wy) * ((1.f - wx) * v00 + wx * v10)
                +        wy  * ((1.f - wx) * v01 + wx * v11);
        outbase[(size_t)o * HW] = v;
    }
}

// ---------------- 5) convex upsample -> [B,2,448,768] ----------------
__global__ void k_up(const float* __restrict__ flow, const float* __restrict__ mask,
                     float* __restrict__ out) {
    int id = blockIdx.x;
    int rs = id & 63;
    int bh = id >> 6;
    int h = bh % H8;
    int b = bh / H8;
    int w = threadIdx.x;
    int r = rs >> 3, s = rs & 7;

    float f0[9], f1v[9];
#pragma unroll
    for (int k = 0; k < 9; k++) {
        int i = k / 3 - 1, j = k % 3 - 1;
        int hh = h + i, ww = w + j;
        bool ok = (hh >= 0 && hh < H8 && ww >= 0 && ww < W8);
        f0[k]  = ok ? flow[((size_t)(b * 2 + 0) * H8 + hh) * W8 + ww] : 0.f;
        f1v[k] = ok ? flow[((size_t)(b * 2 + 1) * H8 + hh) * W8 + ww] : 0.f;
    }
    float e[9], sum = 0.f;
#pragma unroll
    for (int k = 0; k < 9; k++) {
        e[k] = __expf(mask[((size_t)(b * 576 + k * 64 + rs) * H8 + h) * W8 + w]);
        sum += e[k];
    }
    float a0 = 0.f, a1 = 0.f;
#pragma unroll
    for (int k = 0; k < 9; k++) { a0 += e[k] * f0[k]; a1 += e[k] * f1v[k]; }
    float inv = 8.0f / sum;
    int y = h * 8 + r, x = w * 8 + s;
    out[((size_t)(b * 2 + 0) * 448 + y) * 768 + x] = a0 * inv;
    out[((size_t)(b * 2 + 1) * 448 + y) * 768 + x] = a1 * inv;
}

// ---------------- launcher ----------------
extern "C" void kernel_launch(void* const* d_in, const int* in_sizes, int n_in,
                              void* d_out, int out_size) {
    const float* fmap1  = (const float*)d_in[0];
    const float* fmap2  = (const float*)d_in[1];
    const float* coords = (const float*)d_in[2];
    const float* flow   = (const float*)d_in[3];
    const float* mask   = (const float*)d_in[4];
    float* out = (float*)d_out;
    float* out_up = out + (size_t)B_ * 324 * HW;

    dim3 cb(32, 32);
    k_convert<<<dim3(HW / 32, C_ / 32, 4), cb>>>(fmap1, fmap2);     // idx 0
    k_nop<<<1, 32>>>();                                             // idx 1
    k_nop<<<1, 32>>>();                                             // idx 2
    k_gemm<<<dim3(42, 42, 2), 128>>>();                             // idx 3 (profiled)
    k_pool_fused<<<NQ, 256>>>();                                    // idx 4
    k_sample<<<336, dim3(32, 4)>>>(coords, out);                    // idx 5
    k_up<<<NQ * 64 / W8, W8>>>(flow, mask, out_up);                 // idx 6
}

// round 10
// speedup vs baseline: 1.1106x; 1.0615x over previous
#include <cuda_runtime.h>
#include <cuda_fp16.h>
#include <cstdint>

#define B_  2
#define C_  256
#define H8  56
#define W8  96
#define HW  5376            // H8*W8
#define NQ  (B_*HW)         // 10752 query rows (batch-major)

// ---------------- scratch (static __device__, no allocations) ----------------
__device__ __align__(128) __half g_f1[B_*HW*C_];   // fmap1 [b][n][c] fp16
__device__ __align__(128) __half g_f2[B_*HW*C_];   // fmap2 [b][m][c] fp16
__device__ __align__(128) __half g_c0[57802752];   // 2*5376*5376 level-0 corr
__device__ __align__(128) __half g_c1[NQ*28*48];
__device__ __align__(128) __half g_c2[NQ*14*24];
__device__ __align__(128) __half g_c3[NQ*7*12];

// ---------------- helpers ----------------
__device__ __forceinline__ uint32_t smem_u32(const void* p) {
    return (uint32_t)__cvta_generic_to_shared(p);
}
__device__ __forceinline__ void ldm4(uint32_t& r0, uint32_t& r1, uint32_t& r2, uint32_t& r3,
                                     uint32_t addr) {
    asm volatile("ldmatrix.sync.aligned.m8n8.x4.shared.b16 {%0,%1,%2,%3}, [%4];"
                 : "=r"(r0), "=r"(r1), "=r"(r2), "=r"(r3) : "r"(addr));
}
__device__ __forceinline__ void mma16816(float* c, const uint32_t* a, const uint32_t* b) {
    asm volatile(
        "mma.sync.aligned.m16n8k16.row.col.f32.f16.f16.f32 "
        "{%0,%1,%2,%3},{%4,%5,%6,%7},{%8,%9},{%0,%1,%2,%3};"
        : "+f"(c[0]), "+f"(c[1]), "+f"(c[2]), "+f"(c[3])
        : "r"(a[0]), "r"(a[1]), "r"(a[2]), "r"(a[3]), "r"(b[0]), "r"(b[1]));
}
__device__ __forceinline__ void cpasync16(uint32_t dst, const void* src) {
    asm volatile("cp.async.cg.shared.global [%0], [%1], 16;" :: "r"(dst), "l"(src));
}
__device__ __forceinline__ void cp_commit() {
    asm volatile("cp.async.commit_group;" ::: "memory");
}
template<int N> __device__ __forceinline__ void cp_wait() {
    asm volatile("cp.async.wait_group %0;" :: "n"(N) : "memory");
}

// empty kernel: shifts the profiled launch index (3) onto the kernel under study
__global__ void k_nop() {}

// ---------------- 1) transpose + fp16 convert: [B,C,H,W] -> [B,HW,C] ----------------
__global__ void k_convert(const float* __restrict__ f1, const float* __restrict__ f2) {
    __shared__ float tile[32][33];
    int t = blockIdx.z >> 1;
    int b = blockIdx.z & 1;
    const float* src = t ? f2 : f1;
    __half* dst = t ? g_f2 : g_f1;
    int n0 = blockIdx.x * 32, c0 = blockIdx.y * 32;
    int tx = threadIdx.x, ty = threadIdx.y;
    tile[ty][tx] = src[(size_t)(b * C_ + c0 + ty) * HW + n0 + tx];
    __syncthreads();
    dst[(size_t)(b * HW + n0 + ty) * C_ + c0 + tx] = __float2half_rn(tile[tx][ty]);
}

// ---------------- 2) corr GEMM: 128 thr, 4 warps x (64x64), K64 2-stage cp.async ------
#define SSTRIDE 72          // 64 halfs + 8 pad
#define EPSTRIDE 136        // epilogue staging stride (halfs), conflict-free

__global__ __launch_bounds__(128, 2) void k_gemm() {
    __shared__ __align__(16) __half As[2][128 * SSTRIDE];
    __shared__ __align__(16) __half Bs[2][128 * SSTRIDE];
    const int b  = blockIdx.z;
    const int bi = blockIdx.y;
    const int bj = blockIdx.x;
    const int tid  = threadIdx.x;
    const int lane = tid & 31;
    const int wid  = tid >> 5;
    const int wm = (wid & 1) * 64;    // 2 warps along M
    const int wn = (wid >> 1) * 64;   // 2 warps along N

    const __half* Ag = g_f1 + ((size_t)b * HW + (size_t)bi * 128) * C_;
    const __half* Bg = g_f2 + ((size_t)b * HW + (size_t)bj * 128) * C_;

    float acc[4][8][4];
#pragma unroll
    for (int i = 0; i < 4; i++)
#pragma unroll
        for (int j = 0; j < 8; j++)
#pragma unroll
            for (int k = 0; k < 4; k++) acc[i][j][k] = 0.f;

#define LOAD_STAGE64(kt, s)                                                        \
    {                                                                              \
        const int k0 = (kt) * 64;                                                  \
        _Pragma("unroll")                                                          \
        for (int it = 0; it < 8; it++) {                                           \
            int idx = tid + it * 128;          /* 0..1023 */                       \
            int row = idx >> 3;                                                    \
            int c   = (idx & 7) << 3;                                              \
            cpasync16(smem_u32(&As[s][row * SSTRIDE + c]),                         \
                      Ag + row * C_ + k0 + c);                                     \
            cpasync16(smem_u32(&Bs[s][row * SSTRIDE + c]),                         \
                      Bg + row * C_ + k0 + c);                                     \
        }                                                                          \
        cp_commit();                                                               \
    }

    LOAD_STAGE64(0, 0);

#pragma unroll
    for (int kt = 0; kt < 4; kt++) {
        __syncthreads();                     // all warps done with chunk kt-1
        if (kt < 3) { LOAD_STAGE64(kt + 1, (kt + 1) & 1); }
        else        { cp_commit(); }
        cp_wait<1>();                        // chunk kt resident
        __syncthreads();                     // loads of kt visible to all warps
        const __half* as = As[kt & 1];
        const __half* bs = Bs[kt & 1];
#pragma unroll
        for (int kk = 0; kk < 64; kk += 16) {
            uint32_t a[4][4], bf[8][2];
#pragma unroll
            for (int mi = 0; mi < 4; mi++) {
                int row = wm + mi * 16 + (lane & 15);
                int col = kk + ((lane >> 4) << 3);
                ldm4(a[mi][0], a[mi][1], a[mi][2], a[mi][3],
                     smem_u32(as + row * SSTRIDE + col));
            }
#pragma unroll
            for (int nb = 0; nb < 4; nb++) {
                int row = wn + nb * 16 + (lane & 7) + ((lane >> 4) << 3);
                int col = kk + (((lane >> 3) & 1) << 3);
                uint32_t r0, r1, r2, r3;
                ldm4(r0, r1, r2, r3, smem_u32(bs + row * SSTRIDE + col));
                bf[nb * 2][0] = r0; bf[nb * 2][1] = r1;
                bf[nb * 2 + 1][0] = r2; bf[nb * 2 + 1][1] = r3;
            }
#pragma unroll
            for (int mi = 0; mi < 4; mi++)
#pragma unroll
                for (int ni = 0; ni < 8; ni++)
                    mma16816(acc[mi][ni], a[mi], bf[ni]);
        }
    }

    // ---- epilogue: acc -> smem stage (conflict-free) -> coalesced st.128 ----
    __syncthreads();                       // all warps done reading As/Bs
    __half* stage = &As[0][0];             // 128 x EPSTRIDE halfs = 34816 B
    const float s = 0.0625f;               // 1/sqrt(256)
#pragma unroll
    for (int mi = 0; mi < 4; mi++) {
#pragma unroll
        for (int ni = 0; ni < 8; ni++) {
            int r0 = wm + mi * 16 + (lane >> 2);
            int c0 = wn + ni * 8 + (lane & 3) * 2;
            *(__half2*)(stage + r0 * EPSTRIDE + c0) =
                __floats2half2_rn(acc[mi][ni][0] * s, acc[mi][ni][1] * s);
            *(__half2*)(stage + (r0 + 8) * EPSTRIDE + c0) =
                __floats2half2_rn(acc[mi][ni][2] * s, acc[mi][ni][3] * s);
        }
    }
    __syncthreads();
    const size_t rowb = (size_t)b * HW + (size_t)bi * 128;
#pragma unroll
    for (int it = 0; it < 16; it++) {
        int idx = tid + it * 128;
        int r  = idx >> 4;                          // 0..127
        int ci = idx & 15;                          // int4 index within 256B row
        int4 v = *(const int4*)(stage + r * EPSTRIDE + ci * 8);
        *(int4*)(g_c0 + (rowb + r) * HW + (size_t)bj * 128 + ci * 8) = v;
    }
}

// ---------------- 3) fused pyramid pool (pair-vectorized): c0 row -> l1,l2,l3 --------
__global__ __launch_bounds__(256) void k_pool_fused() {
    __shared__ __align__(16) __half s0[56 * 96];
    __shared__ __align__(8)  __half s1[28 * 48];
    __shared__ __align__(8)  __half s2[14 * 24];
    int n = blockIdx.x;
    int tid = threadIdx.x;
    const int4* src = (const int4*)(g_c0 + (size_t)n * 5376);
    int4* s0v = (int4*)s0;
#pragma unroll
    for (int i = tid; i < 672; i += 256) s0v[i] = src[i];
    __syncthreads();

    // level 1: 28x48 outputs as 28x24 half2-pairs; float2 loads (4 halfs/row)
    {
        const float2* r0 = (const float2*)s0;        // 24 float2 per 96-half row
        __half2* d  = (__half2*)s1;
        __half2* g  = (__half2*)(g_c1 + (size_t)n * 1344);
        for (int i = tid; i < 672; i += 256) {       // i = y*24 + j
            int y = i / 24, j = i - y * 24;
            float2 a = r0[(2 * y) * 24 + j];
            float2 b = r0[(2 * y + 1) * 24 + j];
            float2 fa0 = __half22float2(*(const __half2*)&a.x);
            float2 fa1 = __half22float2(*(const __half2*)&a.y);
            float2 fb0 = __half22float2(*(const __half2*)&b.x);
            float2 fb1 = __half22float2(*(const __half2*)&b.y);
            __half2 o = __floats2half2_rn(0.25f * (fa0.x + fa0.y + fb0.x + fb0.y),
                                          0.25f * (fa1.x + fa1.y + fb1.x + fb1.y));
            d[i] = o;
            g[i] = o;
        }
    }
    __syncthreads();

    // level 2: 14x24 outputs as 14x12 pairs
    {
        const float2* r0 = (const float2*)s1;        // 12 float2 per 48-half row
        __half2* d  = (__half2*)s2;
        __half2* g  = (__half2*)(g_c2 + (size_t)n * 336);
        for (int i = tid; i < 168; i += 256) {       // i = y*12 + j
            int y = i / 12, j = i - y * 12;
            float2 a = r0[(2 * y) * 12 + j];
            float2 b = r0[(2 * y + 1) * 12 + j];
            float2 fa0 = __half22float2(*(const __half2*)&a.x);
            float2 fa1 = __half22float2(*(const __half2*)&a.y);
            float2 fb0 = __half22float2(*(const __half2*)&b.x);
            float2 fb1 = __half22float2(*(const __half2*)&b.y);
            __half2 o = __floats2half2_rn(0.25f * (fa0.x + fa0.y + fb0.x + fb0.y),
                                          0.25f * (fa1.x + fa1.y + fb1.x + fb1.y));
            d[i] = o;
            g[i] = o;
        }
    }
    __syncthreads();

    // level 3: 7x12 outputs as 7x6 pairs
    if (tid < 42) {
        const float2* r0 = (const float2*)s2;        // 6 float2 per 24-half row
        __half2* g  = (__half2*)(g_c3 + (size_t)n * 84);
        int y = tid / 6, j = tid - y * 6;
        float2 a = r0[(2 * y) * 6 + j];
        float2 b = r0[(2 * y + 1) * 6 + j];
        float2 fa0 = __half22float2(*(const __half2*)&a.x);
        float2 fa1 = __half22float2(*(const __half2*)&a.y);
        float2 fb0 = __half22float2(*(const __half2*)&b.x);
        float2 fb1 = __half22float2(*(const __half2*)&b.y);
        g[tid] = __floats2half2_rn(0.25f * (fa0.x + fa0.y + fb0.x + fb0.y),
                                   0.25f * (fa1.x + fa1.y + fb1.x + fb1.y));
    }
}

// ---------------- 4) pyramid sampling, coalesced stores -> [B,324,H8,W8] ----------------
__global__ __launch_bounds__(128) void k_sample(const float* __restrict__ coords,
                                                float* __restrict__ out) {
    __shared__ __half swin[4][100][32];
    int blk = blockIdx.x;            // 2*56*3 = 336
    int wseg = blk % 3;
    int h = (blk / 3) % H8;
    int b = blk / (3 * H8);
    int tx = threadIdx.x;            // pixel within 32-segment
    int L  = threadIdx.y;            // level
    int w = wseg * 32 + tx;
    int nq = h * W8 + w;

    float cx = coords[(size_t)(b * 2 + 0) * HW + nq];
    float cy = coords[(size_t)(b * 2 + 1) * HW + nq];

    const __half* cl; int Hl, Wl;
    if (L == 0)      { cl = g_c0; Hl = 56; Wl = 96; }
    else if (L == 1) { cl = g_c1; Hl = 28; Wl = 48; }
    else if (L == 2) { cl = g_c2; Hl = 14; Wl = 24; }
    else             { cl = g_c3; Hl = 7;  Wl = 12; }

    float inv = 1.0f / (float)(1 << L);
    float fx = cx * inv, fy = cy * inv;
    float fxf = floorf(fx), fyf = floorf(fy);
    float wx = fx - fxf, wy = fy - fyf;
    int bx = (int)fxf - 4, by = (int)fyf - 4;

    const __half* base = cl + (size_t)(b * HW + nq) * (Hl * Wl);
#pragma unroll
    for (int ly = 0; ly < 10; ly++) {
        int gy = by + ly;
        bool yok = (gy >= 0) & (gy < Hl);
        const __half* rowp = base + gy * Wl;
#pragma unroll
        for (int lx = 0; lx < 10; lx++) {
            int gx = bx + lx;
            __half v = __float2half_rn(0.f);
            if (yok && gx >= 0 && gx < Wl) v = rowp[gx];
            swin[L][ly * 10 + lx][tx] = v;
        }
    }
    __syncthreads();

    float* outbase = out + ((size_t)(b * 324 + L * 81) * H8 + h) * W8 + w;
#pragma unroll 3
    for (int o = 0; o < 81; o++) {
        int xo = o / 9;              // x varies along axis 0 (torch meshgrid quirk)
        int yo = o % 9;
        float v00 = __half2float(swin[L][yo * 10 + xo][tx]);
        float v10 = __half2float(swin[L][yo * 10 + xo + 1][tx]);
        float v01 = __half2float(swin[L][(yo + 1) * 10 + xo][tx]);
        float v11 = __half2float(swin[L][(yo + 1) * 10 + xo + 1][tx]);
        float v = (1.f - wy) * ((1.f - wx) * v00 + wx * v10)
                +        wy  * ((1.f - wx) * v01 + wx * v11);
        outbase[(size_t)o * HW] = v;
    }
}

// ---------------- 5) convex upsample -> [B,2,448,768] ----------------
__global__ void k_up(const float* __restrict__ flow, const float* __restrict__ mask,
                     float* __restrict__ out) {
    int id = blockIdx.x;
    int rs = id & 63;
    int bh = id >> 6;
    int h = bh % H8;
    int b = bh / H8;
    int w = threadIdx.x;
    int r = rs >> 3, s = rs & 7;

    float f0[9], f1v[9];
#pragma unroll
    for (int k = 0; k < 9; k++) {
        int i = k / 3 - 1, j = k % 3 - 1;
        int hh = h + i, ww = w + j;
        bool ok = (hh >= 0 && hh < H8 && ww >= 0 && ww < W8);
        f0[k]  = ok ? flow[((size_t)(b * 2 + 0) * H8 + hh) * W8 + ww] : 0.f;
        f1v[k] = ok ? flow[((size_t)(b * 2 + 1) * H8 + hh) * W8 + ww] : 0.f;
    }
    float e[9], sum = 0.f;
#pragma unroll
    for (int k = 0; k < 9; k++) {
        e[k] = __expf(mask[((size_t)(b * 576 + k * 64 + rs) * H8 + h) * W8 + w]);
        sum += e[k];
    }
    float a0 = 0.f, a1 = 0.f;
#pragma unroll
    for (int k = 0; k < 9; k++) { a0 += e[k] * f0[k]; a1 += e[k] * f1v[k]; }
    float inv = 8.0f / sum;
    int y = h * 8 + r, x = w * 8 + s;
    out[((size_t)(b * 2 + 0) * 448 + y) * 768 + x] = a0 * inv;
    out[((size_t)(b * 2 + 1) * 448 + y) * 768 + x] = a1 * inv;
}

// ---------------- launcher ----------------
extern "C" void kernel_launch(void* const* d_in, const int* in_sizes, int n_in,
                              void* d_out, int out_size) {
    const float* fmap1  = (const float*)d_in[0];
    const float* fmap2  = (const float*)d_in[1];
    const float* coords = (const float*)d_in[2];
    const float* flow   = (const float*)d_in[3];
    const float* mask   = (const float*)d_in[4];
    float* out = (float*)d_out;
    float* out_up = out + (size_t)B_ * 324 * HW;

    dim3 cb(32, 32);
    k_convert<<<dim3(HW / 32, C_ / 32, 4), cb>>>(fmap1, fmap2);     // idx 0
    k_gemm<<<dim3(42, 42, 2), 128>>>();                             // idx 1
    k_nop<<<1, 32>>>();                                             // idx 2
    k_pool_fused<<<NQ, 256>>>();                                    // idx 3 (profiled)
    k_sample<<<336, dim3(32, 4)>>>(coords, out);                    // idx 4
    k_up<<<NQ * 64 / W8, W8>>>(flow, mask, out_up);                 // idx 5
}

// round 11
// speedup vs baseline: 1.1246x; 1.0127x over previous
#include <cuda_runtime.h>
#include <cuda_fp16.h>
#include <cstdint>

#define B_  2
#define C_  256
#define H8  56
#define W8  96
#define HW  5376            // H8*W8
#define NQ  (B_*HW)         // 10752 query rows (batch-major)

// ---------------- scratch (static __device__, no allocations) ----------------
__device__ __align__(128) __half g_f1[B_*HW*C_];   // fmap1 [b][n][c] fp16
__device__ __align__(128) __half g_f2[B_*HW*C_];   // fmap2 [b][m][c] fp16
__device__ __align__(128) __half g_c0[57802752];   // 2*5376*5376 level-0 corr
__device__ __align__(128) __half g_c1[NQ*28*48];
__device__ __align__(128) __half g_c2[NQ*14*24];
__device__ __align__(128) __half g_c3[NQ*7*12];

// ---------------- helpers ----------------
__device__ __forceinline__ uint32_t smem_u32(const void* p) {
    return (uint32_t)__cvta_generic_to_shared(p);
}
__device__ __forceinline__ void ldm4(uint32_t& r0, uint32_t& r1, uint32_t& r2, uint32_t& r3,
                                     uint32_t addr) {
    asm volatile("ldmatrix.sync.aligned.m8n8.x4.shared.b16 {%0,%1,%2,%3}, [%4];"
                 : "=r"(r0), "=r"(r1), "=r"(r2), "=r"(r3) : "r"(addr));
}
__device__ __forceinline__ void mma16816(float* c, const uint32_t* a, const uint32_t* b) {
    asm volatile(
        "mma.sync.aligned.m16n8k16.row.col.f32.f16.f16.f32 "
        "{%0,%1,%2,%3},{%4,%5,%6,%7},{%8,%9},{%0,%1,%2,%3};"
        : "+f"(c[0]), "+f"(c[1]), "+f"(c[2]), "+f"(c[3])
        : "r"(a[0]), "r"(a[1]), "r"(a[2]), "r"(a[3]), "r"(b[0]), "r"(b[1]));
}
__device__ __forceinline__ void cpasync16(uint32_t dst, const void* src) {
    asm volatile("cp.async.cg.shared.global [%0], [%1], 16;" :: "r"(dst), "l"(src));
}
__device__ __forceinline__ void cp_commit() {
    asm volatile("cp.async.commit_group;" ::: "memory");
}
template<int N> __device__ __forceinline__ void cp_wait() {
    asm volatile("cp.async.wait_group %0;" :: "n"(N) : "memory");
}

// ---------------- 1) transpose + fp16 convert: [B,C,H,W] -> [B,HW,C] ----------------
__global__ void k_convert(const float* __restrict__ f1, const float* __restrict__ f2) {
    __shared__ float tile[32][33];
    int t = blockIdx.z >> 1;
    int b = blockIdx.z & 1;
    const float* src = t ? f2 : f1;
    __half* dst = t ? g_f2 : g_f1;
    int n0 = blockIdx.x * 32, c0 = blockIdx.y * 32;
    int tx = threadIdx.x, ty = threadIdx.y;
    tile[ty][tx] = src[(size_t)(b * C_ + c0 + ty) * HW + n0 + tx];
    __syncthreads();
    dst[(size_t)(b * HW + n0 + ty) * C_ + c0 + tx] = __float2half_rn(tile[tx][ty]);
}

// ---------------- 2) corr GEMM: 128 thr, 4 warps x (64x64), K64 2-stage cp.async ------
#define SSTRIDE 72          // 64 halfs + 8 pad
#define EPSTRIDE 136        // epilogue staging stride (halfs), conflict-free

__global__ __launch_bounds__(128, 2) void k_gemm() {
    __shared__ __align__(16) __half As[2][128 * SSTRIDE];
    __shared__ __align__(16) __half Bs[2][128 * SSTRIDE];
    const int b  = blockIdx.z;
    const int bi = blockIdx.y;
    const int bj = blockIdx.x;
    const int tid  = threadIdx.x;
    const int lane = tid & 31;
    const int wid  = tid >> 5;
    const int wm = (wid & 1) * 64;    // 2 warps along M
    const int wn = (wid >> 1) * 64;   // 2 warps along N

    const __half* Ag = g_f1 + ((size_t)b * HW + (size_t)bi * 128) * C_;
    const __half* Bg = g_f2 + ((size_t)b * HW + (size_t)bj * 128) * C_;

    float acc[4][8][4];
#pragma unroll
    for (int i = 0; i < 4; i++)
#pragma unroll
        for (int j = 0; j < 8; j++)
#pragma unroll
            for (int k = 0; k < 4; k++) acc[i][j][k] = 0.f;

#define LOAD_STAGE64(kt, s)                                                        \
    {                                                                              \
        const int k0 = (kt) * 64;                                                  \
        _Pragma("unroll")                                                          \
        for (int it = 0; it < 8; it++) {                                           \
            int idx = tid + it * 128;          /* 0..1023 */                       \
            int row = idx >> 3;                                                    \
            int c   = (idx & 7) << 3;                                              \
            cpasync16(smem_u32(&As[s][row * SSTRIDE + c]),                         \
                      Ag + row * C_ + k0 + c);                                     \
            cpasync16(smem_u32(&Bs[s][row * SSTRIDE + c]),                         \
                      Bg + row * C_ + k0 + c);                                     \
        }                                                                          \
        cp_commit();                                                               \
    }

    LOAD_STAGE64(0, 0);

#pragma unroll
    for (int kt = 0; kt < 4; kt++) {
        __syncthreads();                     // all warps done with chunk kt-1
        if (kt < 3) { LOAD_STAGE64(kt + 1, (kt + 1) & 1); }
        else        { cp_commit(); }
        cp_wait<1>();                        // chunk kt resident
        __syncthreads();                     // loads of kt visible to all warps
        const __half* as = As[kt & 1];
        const __half* bs = Bs[kt & 1];
#pragma unroll
        for (int kk = 0; kk < 64; kk += 16) {
            uint32_t a[4][4], bf[8][2];
#pragma unroll
            for (int mi = 0; mi < 4; mi++) {
                int row = wm + mi * 16 + (lane & 15);
                int col = kk + ((lane >> 4) << 3);
                ldm4(a[mi][0], a[mi][1], a[mi][2], a[mi][3],
                     smem_u32(as + row * SSTRIDE + col));
            }
#pragma unroll
            for (int nb = 0; nb < 4; nb++) {
                int row = wn + nb * 16 + (lane & 7) + ((lane >> 4) << 3);
                int col = kk + (((lane >> 3) & 1) << 3);
                uint32_t r0, r1, r2, r3;
                ldm4(r0, r1, r2, r3, smem_u32(bs + row * SSTRIDE + col));
                bf[nb * 2][0] = r0; bf[nb * 2][1] = r1;
                bf[nb * 2 + 1][0] = r2; bf[nb * 2 + 1][1] = r3;
            }
#pragma unroll
            for (int mi = 0; mi < 4; mi++)
#pragma unroll
                for (int ni = 0; ni < 8; ni++)
                    mma16816(acc[mi][ni], a[mi], bf[ni]);
        }
    }

    // ---- epilogue: acc -> smem stage (conflict-free) -> coalesced st.128 ----
    __syncthreads();                       // all warps done reading As/Bs
    __half* stage = &As[0][0];             // 128 x EPSTRIDE halfs = 34816 B
    const float s = 0.0625f;               // 1/sqrt(256)
#pragma unroll
    for (int mi = 0; mi < 4; mi++) {
#pragma unroll
        for (int ni = 0; ni < 8; ni++) {
            int r0 = wm + mi * 16 + (lane >> 2);
            int c0 = wn + ni * 8 + (lane & 3) * 2;
            *(__half2*)(stage + r0 * EPSTRIDE + c0) =
                __floats2half2_rn(acc[mi][ni][0] * s, acc[mi][ni][1] * s);
            *(__half2*)(stage + (r0 + 8) * EPSTRIDE + c0) =
                __floats2half2_rn(acc[mi][ni][2] * s, acc[mi][ni][3] * s);
        }
    }
    __syncthreads();
    const size_t rowb = (size_t)b * HW + (size_t)bi * 128;
#pragma unroll
    for (int it = 0; it < 16; it++) {
        int idx = tid + it * 128;
        int r  = idx >> 4;                          // 0..127
        int ci = idx & 15;                          // int4 index within 256B row
        int4 v = *(const int4*)(stage + r * EPSTRIDE + ci * 8);
        *(int4*)(g_c0 + (rowb + r) * HW + (size_t)bj * 128 + ci * 8) = v;
    }
}

// ---------------- 3) fused pyramid pool (pair-vectorized): c0 row -> l1,l2,l3 --------
__global__ __launch_bounds__(256) void k_pool_fused() {
    __shared__ __align__(16) __half s0[56 * 96];
    __shared__ __align__(8)  __half s1[28 * 48];
    __shared__ __align__(8)  __half s2[14 * 24];
    int n = blockIdx.x;
    int tid = threadIdx.x;
    const int4* src = (const int4*)(g_c0 + (size_t)n * 5376);
    int4* s0v = (int4*)s0;
#pragma unroll
    for (int i = tid; i < 672; i += 256) s0v[i] = src[i];
    __syncthreads();

    {
        const float2* r0 = (const float2*)s0;        // 24 float2 per 96-half row
        __half2* d  = (__half2*)s1;
        __half2* g  = (__half2*)(g_c1 + (size_t)n * 1344);
        for (int i = tid; i < 672; i += 256) {       // i = y*24 + j
            int y = i / 24, j = i - y * 24;
            float2 a = r0[(2 * y) * 24 + j];
            float2 b = r0[(2 * y + 1) * 24 + j];
            float2 fa0 = __half22float2(*(const __half2*)&a.x);
            float2 fa1 = __half22float2(*(const __half2*)&a.y);
            float2 fb0 = __half22float2(*(const __half2*)&b.x);
            float2 fb1 = __half22float2(*(const __half2*)&b.y);
            __half2 o = __floats2half2_rn(0.25f * (fa0.x + fa0.y + fb0.x + fb0.y),
                                          0.25f * (fa1.x + fa1.y + fb1.x + fb1.y));
            d[i] = o;
            g[i] = o;
        }
    }
    __syncthreads();

    {
        const float2* r0 = (const float2*)s1;        // 12 float2 per 48-half row
        __half2* d  = (__half2*)s2;
        __half2* g  = (__half2*)(g_c2 + (size_t)n * 336);
        for (int i = tid; i < 168; i += 256) {       // i = y*12 + j
            int y = i / 12, j = i - y * 12;
            float2 a = r0[(2 * y) * 12 + j];
            float2 b = r0[(2 * y + 1) * 12 + j];
            float2 fa0 = __half22float2(*(const __half2*)&a.x);
            float2 fa1 = __half22float2(*(const __half2*)&a.y);
            float2 fb0 = __half22float2(*(const __half2*)&b.x);
            float2 fb1 = __half22float2(*(const __half2*)&b.y);
            __half2 o = __floats2half2_rn(0.25f * (fa0.x + fa0.y + fb0.x + fb0.y),
                                          0.25f * (fa1.x + fa1.y + fb1.x + fb1.y));
            d[i] = o;
            g[i] = o;
        }
    }
    __syncthreads();

    if (tid < 42) {
        const float2* r0 = (const float2*)s2;        // 6 float2 per 24-half row
        __half2* g  = (__half2*)(g_c3 + (size_t)n * 84);
        int y = tid / 6, j = tid - y * 6;
        float2 a = r0[(2 * y) * 6 + j];
        float2 b = r0[(2 * y + 1) * 6 + j];
        float2 fa0 = __half22float2(*(const __half2*)&a.x);
        float2 fa1 = __half22float2(*(const __half2*)&a.y);
        float2 fb0 = __half22float2(*(const __half2*)&b.x);
        float2 fb1 = __half22float2(*(const __half2*)&b.y);
        g[tid] = __floats2half2_rn(0.25f * (fa0.x + fa0.y + fb0.x + fb0.y),
                                   0.25f * (fa1.x + fa1.y + fb1.x + fb1.y));
    }
}

// ---------------- 4) pyramid sampling -> [B,324,H8,W8] ----------------
// Block = 32 pixels x 8 warps (2 per level). Each warp-half loads 5 window rows
// and emits 41/40 channels; stores stay 128B-coalesced across pixels.
__global__ __launch_bounds__(256) void k_sample(const float* __restrict__ coords,
                                                float* __restrict__ out) {
    __shared__ __half swin[4][100][32];
    int blk = blockIdx.x;            // 2*56*3 = 336
    int wseg = blk % 3;
    int h = (blk / 3) % H8;
    int b = blk / (3 * H8);
    int tx = threadIdx.x;            // pixel within 32-segment
    int ty = threadIdx.y;            // 0..7
    int L    = ty >> 1;              // level
    int half = ty & 1;
    int w = wseg * 32 + tx;
    int nq = h * W8 + w;

    float cx = coords[(size_t)(b * 2 + 0) * HW + nq];
    float cy = coords[(size_t)(b * 2 + 1) * HW + nq];

    const __half* cl; int Hl, Wl;
    if (L == 0)      { cl = g_c0; Hl = 56; Wl = 96; }
    else if (L == 1) { cl = g_c1; Hl = 28; Wl = 48; }
    else if (L == 2) { cl = g_c2; Hl = 14; Wl = 24; }
    else             { cl = g_c3; Hl = 7;  Wl = 12; }

    float inv = 1.0f / (float)(1 << L);
    float fx = cx * inv, fy = cy * inv;
    float fxf = floorf(fx), fyf = floorf(fy);
    float wx = fx - fxf, wy = fy - fyf;
    int bx = (int)fxf - 4, by = (int)fyf - 4;

    const __half* base = cl + (size_t)(b * HW + nq) * (Hl * Wl);
    // this half loads window rows [half*5, half*5+5)
#pragma unroll
    for (int lyi = 0; lyi < 5; lyi++) {
        int ly = half * 5 + lyi;
        int gy = by + ly;
        bool yok = (gy >= 0) & (gy < Hl);
        const __half* rowp = base + gy * Wl;
#pragma unroll
        for (int lx = 0; lx < 10; lx++) {
            int gx = bx + lx;
            __half v = __float2half_rn(0.f);
            if (yok && gx >= 0 && gx < Wl) v = rowp[gx];
            swin[L][ly * 10 + lx][tx] = v;
        }
    }
    __syncthreads();

    float* outbase = out + ((size_t)(b * 324 + L * 81) * H8 + h) * W8 + w;
    int o0   = half ? 41 : 0;
    int oend = half ? 81 : 41;
    float omwx = 1.f - wx, omwy = 1.f - wy;
    for (int o = o0; o < oend; o++) {
        int xo = o / 9;              // x varies along axis 0 (torch meshgrid quirk)
        int yo = o - xo * 9;
        float v00 = __half2float(swin[L][yo * 10 + xo][tx]);
        float v10 = __half2float(swin[L][yo * 10 + xo + 1][tx]);
        float v01 = __half2float(swin[L][(yo + 1) * 10 + xo][tx]);
        float v11 = __half2float(swin[L][(yo + 1) * 10 + xo + 1][tx]);
        float v = omwy * (omwx * v00 + wx * v10) + wy * (omwx * v01 + wx * v11);
        outbase[(size_t)o * HW] = v;
    }
}

// ---------------- 5) convex upsample -> [B,2,448,768] ----------------
__global__ void k_up(const float* __restrict__ flow, const float* __restrict__ mask,
                     float* __restrict__ out) {
    int id = blockIdx.x;
    int rs = id & 63;
    int bh = id >> 6;
    int h = bh % H8;
    int b = bh / H8;
    int w = threadIdx.x;
    int r = rs >> 3, s = rs & 7;

    float f0[9], f1v[9];
#pragma unroll
    for (int k = 0; k < 9; k++) {
        int i = k / 3 - 1, j = k % 3 - 1;
        int hh = h + i, ww = w + j;
        bool ok = (hh >= 0 && hh < H8 && ww >= 0 && ww < W8);
        f0[k]  = ok ? flow[((size_t)(b * 2 + 0) * H8 + hh) * W8 + ww] : 0.f;
        f1v[k] = ok ? flow[((size_t)(b * 2 + 1) * H8 + hh) * W8 + ww] : 0.f;
    }
    float e[9], sum = 0.f;
#pragma unroll
    for (int k = 0; k < 9; k++) {
        e[k] = __expf(mask[((size_t)(b * 576 + k * 64 + rs) * H8 + h) * W8 + w]);
        sum += e[k];
    }
    float a0 = 0.f, a1 = 0.f;
#pragma unroll
    for (int k = 0; k < 9; k++) { a0 += e[k] * f0[k]; a1 += e[k] * f1v[k]; }
    float inv = 8.0f / sum;
    int y = h * 8 + r, x = w * 8 + s;
    out[((size_t)(b * 2 + 0) * 448 + y) * 768 + x] = a0 * inv;
    out[((size_t)(b * 2 + 1) * 448 + y) * 768 + x] = a1 * inv;
}

// ---------------- launcher (k_up forked onto a side stream) ----------------
extern "C" void kernel_launch(void* const* d_in, const int* in_sizes, int n_in,
                              void* d_out, int out_size) {
    const float* fmap1  = (const float*)d_in[0];
    const float* fmap2  = (const float*)d_in[1];
    const float* coords = (const float*)d_in[2];
    const float* flow   = (const float*)d_in[3];
    const float* mask   = (const float*)d_in[4];
    float* out = (float*)d_out;
    float* out_up = out + (size_t)B_ * 324 * HW;

    // created once, on the (uncaptured) first call — no API creation during capture
    static cudaStream_t s2 = [] {
        cudaStream_t s; cudaStreamCreateWithFlags(&s, cudaStreamNonBlocking); return s;
    }();
    static cudaEvent_t e_fork = [] {
        cudaEvent_t e; cudaEventCreateWithFlags(&e, cudaEventDisableTiming); return e;
    }();
    static cudaEvent_t e_join = [] {
        cudaEvent_t e; cudaEventCreateWithFlags(&e, cudaEventDisableTiming); return e;
    }();

    dim3 cb(32, 32);
    // main chain on the capture (legacy) stream:
    k_convert<<<dim3(HW / 32, C_ / 32, 4), cb>>>(fmap1, fmap2);     // idx 0
    k_gemm<<<dim3(42, 42, 2), 128>>>();                             // idx 1
    k_pool_fused<<<NQ, 256>>>();                                    // idx 2
    k_sample<<<336, dim3(32, 8)>>>(coords, out);                    // idx 3 (profiled)

    // independent branch: k_up runs concurrently with the gemm chain
    cudaEventRecord(e_fork, 0);                 // fork point (captured)
    cudaStreamWaitEvent(s2, e_fork, 0);
    k_up<<<NQ * 64 / W8, W8, 0, s2>>>(flow, mask, out_up);
    cudaEventRecord(e_join, s2);
    cudaStreamWaitEvent(0, e_join, 0);          // join back before return
}

// round 12
// speedup vs baseline: 1.1709x; 1.0412x over previous
#include <cuda_runtime.h>
#include <cuda_fp16.h>
#include <cstdint>

#define B_  2
#define C_  256
#define H8  56
#define W8  96
#define HW  5376            // H8*W8
#define NQ  (B_*HW)         // 10752 query rows (batch-major)

// ---------------- scratch (static __device__, no allocations) ----------------
__device__ __align__(128) __half g_f1[B_*HW*C_];   // fmap1 [b][n][c] fp16
__device__ __align__(128) __half g_f2[B_*HW*C_];   // fmap2 [b][m][c] fp16
__device__ __align__(128) __half g_c0[57802752];   // 2*5376*5376 level-0 corr
__device__ __align__(128) __half g_c1[NQ*28*48];
__device__ __align__(128) __half g_c2[NQ*14*24];
__device__ __align__(128) __half g_c3[NQ*7*12];

// ---------------- helpers ----------------
__device__ __forceinline__ uint32_t smem_u32(const void* p) {
    return (uint32_t)__cvta_generic_to_shared(p);
}
__device__ __forceinline__ void ldm4(uint32_t& r0, uint32_t& r1, uint32_t& r2, uint32_t& r3,
                                     uint32_t addr) {
    asm volatile("ldmatrix.sync.aligned.m8n8.x4.shared.b16 {%0,%1,%2,%3}, [%4];"
                 : "=r"(r0), "=r"(r1), "=r"(r2), "=r"(r3) : "r"(addr));
}
__device__ __forceinline__ void mma16816(float* c, const uint32_t* a, const uint32_t* b) {
    asm volatile(
        "mma.sync.aligned.m16n8k16.row.col.f32.f16.f16.f32 "
        "{%0,%1,%2,%3},{%4,%5,%6,%7},{%8,%9},{%0,%1,%2,%3};"
        : "+f"(c[0]), "+f"(c[1]), "+f"(c[2]), "+f"(c[3])
        : "r"(a[0]), "r"(a[1]), "r"(a[2]), "r"(a[3]), "r"(b[0]), "r"(b[1]));
}
__device__ __forceinline__ void cpasync16(uint32_t dst, const void* src) {
    asm volatile("cp.async.cg.shared.global [%0], [%1], 16;" :: "r"(dst), "l"(src));
}
__device__ __forceinline__ void cp_commit() {
    asm volatile("cp.async.commit_group;" ::: "memory");
}
template<int N> __device__ __forceinline__ void cp_wait() {
    asm volatile("cp.async.wait_group %0;" :: "n"(N) : "memory");
}

// ---------------- 1) transpose + fp16 convert: [B,C,H,W] -> [B,HW,C] ----------------
__global__ void k_convert(const float* __restrict__ f1, const float* __restrict__ f2) {
    __shared__ float tile[32][33];
    int t = blockIdx.z >> 1;
    int b = blockIdx.z & 1;
    const float* src = t ? f2 : f1;
    __half* dst = t ? g_f2 : g_f1;
    int n0 = blockIdx.x * 32, c0 = blockIdx.y * 32;
    int tx = threadIdx.x, ty = threadIdx.y;
    tile[ty][tx] = src[(size_t)(b * C_ + c0 + ty) * HW + n0 + tx];
    __syncthreads();
    dst[(size_t)(b * HW + n0 + ty) * C_ + c0 + tx] = __float2half_rn(tile[tx][ty]);
}

// ---------------- 2) corr GEMM: 128 thr, 4 warps x (64x64), K64 2-stage cp.async ------
#define SSTRIDE 72          // 64 halfs + 8 pad
#define EPSTRIDE 136        // epilogue staging stride (halfs), conflict-free

__global__ __launch_bounds__(128, 2) void k_gemm() {
    __shared__ __align__(16) __half As[2][128 * SSTRIDE];
    __shared__ __align__(16) __half Bs[2][128 * SSTRIDE];
    const int b  = blockIdx.z;
    const int bi = blockIdx.y;
    const int bj = blockIdx.x;
    const int tid  = threadIdx.x;
    const int lane = tid & 31;
    const int wid  = tid >> 5;
    const int wm = (wid & 1) * 64;    // 2 warps along M
    const int wn = (wid >> 1) * 64;   // 2 warps along N

    const __half* Ag = g_f1 + ((size_t)b * HW + (size_t)bi * 128) * C_;
    const __half* Bg = g_f2 + ((size_t)b * HW + (size_t)bj * 128) * C_;

    float acc[4][8][4];
#pragma unroll
    for (int i = 0; i < 4; i++)
#pragma unroll
        for (int j = 0; j < 8; j++)
#pragma unroll
            for (int k = 0; k < 4; k++) acc[i][j][k] = 0.f;

#define LOAD_STAGE64(kt, s)                                                        \
    {                                                                              \
        const int k0 = (kt) * 64;                                                  \
        _Pragma("unroll")                                                          \
        for (int it = 0; it < 8; it++) {                                           \
            int idx = tid + it * 128;          /* 0..1023 */                       \
            int row = idx >> 3;                                                    \
            int c   = (idx & 7) << 3;                                              \
            cpasync16(smem_u32(&As[s][row * SSTRIDE + c]),                         \
                      Ag + row * C_ + k0 + c);                                     \
            cpasync16(smem_u32(&Bs[s][row * SSTRIDE + c]),                         \
                      Bg + row * C_ + k0 + c);                                     \
        }                                                                          \
        cp_commit();                                                               \
    }

    LOAD_STAGE64(0, 0);

#pragma unroll
    for (int kt = 0; kt < 4; kt++) {
        __syncthreads();                     // all warps done with chunk kt-1
        if (kt < 3) { LOAD_STAGE64(kt + 1, (kt + 1) & 1); }
        else        { cp_commit(); }
        cp_wait<1>();                        // chunk kt resident
        __syncthreads();                     // loads of kt visible to all warps
        const __half* as = As[kt & 1];
        const __half* bs = Bs[kt & 1];
#pragma unroll
        for (int kk = 0; kk < 64; kk += 16) {
            uint32_t a[4][4], bf[8][2];
#pragma unroll
            for (int mi = 0; mi < 4; mi++) {
                int row = wm + mi * 16 + (lane & 15);
                int col = kk + ((lane >> 4) << 3);
                ldm4(a[mi][0], a[mi][1], a[mi][2], a[mi][3],
                     smem_u32(as + row * SSTRIDE + col));
            }
#pragma unroll
            for (int nb = 0; nb < 4; nb++) {
                int row = wn + nb * 16 + (lane & 7) + ((lane >> 4) << 3);
                int col = kk + (((lane >> 3) & 1) << 3);
                uint32_t r0, r1, r2, r3;
                ldm4(r0, r1, r2, r3, smem_u32(bs + row * SSTRIDE + col));
                bf[nb * 2][0] = r0; bf[nb * 2][1] = r1;
                bf[nb * 2 + 1][0] = r2; bf[nb * 2 + 1][1] = r3;
            }
#pragma unroll
            for (int mi = 0; mi < 4; mi++)
#pragma unroll
                for (int ni = 0; ni < 8; ni++)
                    mma16816(acc[mi][ni], a[mi], bf[ni]);
        }
    }

    // ---- epilogue: acc -> smem stage (conflict-free) -> coalesced st.128 ----
    __syncthreads();                       // all warps done reading As/Bs
    __half* stage = &As[0][0];             // 128 x EPSTRIDE halfs = 34816 B
    const float s = 0.0625f;               // 1/sqrt(256)
#pragma unroll
    for (int mi = 0; mi < 4; mi++) {
#pragma unroll
        for (int ni = 0; ni < 8; ni++) {
            int r0 = wm + mi * 16 + (lane >> 2);
            int c0 = wn + ni * 8 + (lane & 3) * 2;
            *(__half2*)(stage + r0 * EPSTRIDE + c0) =
                __floats2half2_rn(acc[mi][ni][0] * s, acc[mi][ni][1] * s);
            *(__half2*)(stage + (r0 + 8) * EPSTRIDE + c0) =
                __floats2half2_rn(acc[mi][ni][2] * s, acc[mi][ni][3] * s);
        }
    }
    __syncthreads();
    const size_t rowb = (size_t)b * HW + (size_t)bi * 128;
#pragma unroll
    for (int it = 0; it < 16; it++) {
        int idx = tid + it * 128;
        int r  = idx >> 4;                          // 0..127
        int ci = idx & 15;                          // int4 index within 256B row
        int4 v = *(const int4*)(stage + r * EPSTRIDE + ci * 8);
        *(int4*)(g_c0 + (rowb + r) * HW + (size_t)bj * 128 + ci * 8) = v;
    }
}

// ---------------- 3) fused pyramid pool (pair-vectorized): c0 row -> l1,l2,l3 --------
__global__ __launch_bounds__(256) void k_pool_fused() {
    __shared__ __align__(16) __half s0[56 * 96];
    __shared__ __align__(8)  __half s1[28 * 48];
    __shared__ __align__(8)  __half s2[14 * 24];
    int n = blockIdx.x;
    int tid = threadIdx.x;
    const int4* src = (const int4*)(g_c0 + (size_t)n * 5376);
    int4* s0v = (int4*)s0;
#pragma unroll
    for (int i = tid; i < 672; i += 256) s0v[i] = src[i];
    __syncthreads();

    {
        const float2* r0 = (const float2*)s0;        // 24 float2 per 96-half row
        __half2* d  = (__half2*)s1;
        __half2* g  = (__half2*)(g_c1 + (size_t)n * 1344);
        for (int i = tid; i < 672; i += 256) {       // i = y*24 + j
            int y = i / 24, j = i - y * 24;
            float2 a = r0[(2 * y) * 24 + j];
            float2 b = r0[(2 * y + 1) * 24 + j];
            float2 fa0 = __half22float2(*(const __half2*)&a.x);
            float2 fa1 = __half22float2(*(const __half2*)&a.y);
            float2 fb0 = __half22float2(*(const __half2*)&b.x);
            float2 fb1 = __half22float2(*(const __half2*)&b.y);
            __half2 o = __floats2half2_rn(0.25f * (fa0.x + fa0.y + fb0.x + fb0.y),
                                          0.25f * (fa1.x + fa1.y + fb1.x + fb1.y));
            d[i] = o;
            g[i] = o;
        }
    }
    __syncthreads();

    {
        const float2* r0 = (const float2*)s1;        // 12 float2 per 48-half row
        __half2* d  = (__half2*)s2;
        __half2* g  = (__half2*)(g_c2 + (size_t)n * 336);
        for (int i = tid; i < 168; i += 256) {       // i = y*12 + j
            int y = i / 12, j = i - y * 12;
            float2 a = r0[(2 * y) * 12 + j];
            float2 b = r0[(2 * y + 1) * 12 + j];
            float2 fa0 = __half22float2(*(const __half2*)&a.x);
            float2 fa1 = __half22float2(*(const __half2*)&a.y);
            float2 fb0 = __half22float2(*(const __half2*)&b.x);
            float2 fb1 = __half22float2(*(const __half2*)&b.y);
            __half2 o = __floats2half2_rn(0.25f * (fa0.x + fa0.y + fb0.x + fb0.y),
                                          0.25f * (fa1.x + fa1.y + fb1.x + fb1.y));
            d[i] = o;
            g[i] = o;
        }
    }
    __syncthreads();

    if (tid < 42) {
        const float2* r0 = (const float2*)s2;        // 6 float2 per 24-half row
        __half2* g  = (__half2*)(g_c3 + (size_t)n * 84);
        int y = tid / 6, j = tid - y * 6;
        float2 a = r0[(2 * y) * 6 + j];
        float2 b = r0[(2 * y + 1) * 6 + j];
        float2 fa0 = __half22float2(*(const __half2*)&a.x);
        float2 fa1 = __half22float2(*(const __half2*)&a.y);
        float2 fb0 = __half22float2(*(const __half2*)&b.x);
        float2 fb1 = __half22float2(*(const __half2*)&b.y);
        g[tid] = __floats2half2_rn(0.25f * (fa0.x + fa0.y + fb0.x + fb0.y),
                                   0.25f * (fa1.x + fa1.y + fb1.x + fb1.y));
    }
}

// ---------------- 4) pyramid sampling -> [B,324,H8,W8] ----------------
// Block = 32 pixels x 2 warps, one LEVEL per block (grid 336*4).
// Each warp-half loads 5 window rows and emits 41/40 channels; coalesced stores.
__global__ __launch_bounds__(64) void k_sample(const float* __restrict__ coords,
                                               float* __restrict__ out) {
    __shared__ __half swin[100][32];
    int blk = blockIdx.x;            // (b,h,seg) in [0,336), L = blockIdx.y
    int L = blockIdx.y;
    int wseg = blk % 3;
    int h = (blk / 3) % H8;
    int b = blk / (3 * H8);
    int tx = threadIdx.x;            // pixel within 32-segment
    int half = threadIdx.y;          // 0..1
    int w = wseg * 32 + tx;
    int nq = h * W8 + w;

    float cx = coords[(size_t)(b * 2 + 0) * HW + nq];
    float cy = coords[(size_t)(b * 2 + 1) * HW + nq];

    const __half* cl; int Hl, Wl;
    if (L == 0)      { cl = g_c0; Hl = 56; Wl = 96; }
    else if (L == 1) { cl = g_c1; Hl = 28; Wl = 48; }
    else if (L == 2) { cl = g_c2; Hl = 14; Wl = 24; }
    else             { cl = g_c3; Hl = 7;  Wl = 12; }

    float inv = 1.0f / (float)(1 << L);
    float fx = cx * inv, fy = cy * inv;
    float fxf = floorf(fx), fyf = floorf(fy);
    float wx = fx - fxf, wy = fy - fyf;
    int bx = (int)fxf - 4, by = (int)fyf - 4;

    const __half* base = cl + (size_t)(b * HW + nq) * (Hl * Wl);
    // this half loads window rows [half*5, half*5+5)
#pragma unroll
    for (int lyi = 0; lyi < 5; lyi++) {
        int ly = half * 5 + lyi;
        int gy = by + ly;
        bool yok = (gy >= 0) & (gy < Hl);
        const __half* rowp = base + gy * Wl;
#pragma unroll
        for (int lx = 0; lx < 10; lx++) {
            int gx = bx + lx;
            __half v = __float2half_rn(0.f);
            if (yok && gx >= 0 && gx < Wl) v = rowp[gx];
            swin[ly * 10 + lx][tx] = v;
        }
    }
    __syncthreads();

    float* outbase = out + ((size_t)(b * 324 + L * 81) * H8 + h) * W8 + w;
    int o0   = half ? 41 : 0;
    int oend = half ? 81 : 41;
    float omwx = 1.f - wx, omwy = 1.f - wy;
    for (int o = o0; o < oend; o++) {
        int xo = o / 9;              // x varies along axis 0 (torch meshgrid quirk)
        int yo = o - xo * 9;
        float v00 = __half2float(swin[yo * 10 + xo][tx]);
        float v10 = __half2float(swin[yo * 10 + xo + 1][tx]);
        float v01 = __half2float(swin[(yo + 1) * 10 + xo][tx]);
        float v11 = __half2float(swin[(yo + 1) * 10 + xo + 1][tx]);
        float v = omwy * (omwx * v00 + wx * v10) + wy * (omwx * v01 + wx * v11);
        outbase[(size_t)o * HW] = v;
    }
}

// ---------------- 5) convex upsample -> [B,2,448,768] ----------------
__global__ void k_up(const float* __restrict__ flow, const float* __restrict__ mask,
                     float* __restrict__ out) {
    int id = blockIdx.x;
    int rs = id & 63;
    int bh = id >> 6;
    int h = bh % H8;
    int b = bh / H8;
    int w = threadIdx.x;
    int r = rs >> 3, s = rs & 7;

    float f0[9], f1v[9];
#pragma unroll
    for (int k = 0; k < 9; k++) {
        int i = k / 3 - 1, j = k % 3 - 1;
        int hh = h + i, ww = w + j;
        bool ok = (hh >= 0 && hh < H8 && ww >= 0 && ww < W8);
        f0[k]  = ok ? flow[((size_t)(b * 2 + 0) * H8 + hh) * W8 + ww] : 0.f;
        f1v[k] = ok ? flow[((size_t)(b * 2 + 1) * H8 + hh) * W8 + ww] : 0.f;
    }
    float e[9], sum = 0.f;
#pragma unroll
    for (int k = 0; k < 9; k++) {
        e[k] = __expf(mask[((size_t)(b * 576 + k * 64 + rs) * H8 + h) * W8 + w]);
        sum += e[k];
    }
    float a0 = 0.f, a1 = 0.f;
#pragma unroll
    for (int k = 0; k < 9; k++) { a0 += e[k] * f0[k]; a1 += e[k] * f1v[k]; }
    float inv = 8.0f / sum;
    int y = h * 8 + r, x = w * 8 + s;
    out[((size_t)(b * 2 + 0) * 448 + y) * 768 + x] = a0 * inv;
    out[((size_t)(b * 2 + 1) * 448 + y) * 768 + x] = a1 * inv;
}

// ---------------- launcher (k_up forked at graph head) ----------------
extern "C" void kernel_launch(void* const* d_in, const int* in_sizes, int n_in,
                              void* d_out, int out_size) {
    const float* fmap1  = (const float*)d_in[0];
    const float* fmap2  = (const float*)d_in[1];
    const float* coords = (const float*)d_in[2];
    const float* flow   = (const float*)d_in[3];
    const float* mask   = (const float*)d_in[4];
    float* out = (float*)d_out;
    float* out_up = out + (size_t)B_ * 324 * HW;

    // created once, on the (uncaptured) first call — no API creation during capture
    static cudaStream_t s2 = [] {
        cudaStream_t s; cudaStreamCreateWithFlags(&s, cudaStreamNonBlocking); return s;
    }();
    static cudaEvent_t e_fork = [] {
        cudaEvent_t e; cudaEventCreateWithFlags(&e, cudaEventDisableTiming); return e;
    }();
    static cudaEvent_t e_join = [] {
        cudaEvent_t e; cudaEventCreateWithFlags(&e, cudaEventDisableTiming); return e;
    }();

    // fork FIRST: k_up depends only on inputs, overlaps with convert+gemm
    cudaEventRecord(e_fork, 0);
    cudaStreamWaitEvent(s2, e_fork, 0);
    k_up<<<NQ * 64 / W8, W8, 0, s2>>>(flow, mask, out_up);
    cudaEventRecord(e_join, s2);

    dim3 cb(32, 32);
    k_convert<<<dim3(HW / 32, C_ / 32, 4), cb>>>(fmap1, fmap2);     // idx 0 (main)
    k_gemm<<<dim3(42, 42, 2), 128>>>();                             // idx 1
    k_pool_fused<<<NQ, 256>>>();                                    // idx 2
    k_sample<<<dim3(336, 4), dim3(32, 2)>>>(coords, out);           // idx 3 (profiled)

    cudaStreamWaitEvent(0, e_join, 0);          // join before return
}